// round 11
// baseline (speedup 1.0000x reference)
#include <cuda_runtime.h>
#include <cuda_bf16.h>
#include <cstdint>

#define Bb   64
#define Tt   256
#define Ii   512
#define Oo   512
#define NOBS 128
#define ETA  0.01f
#define CH   32
#define NCH  (Tt / CH)

typedef unsigned long long u64;

// ---- scratch (static __device__, no allocs) ----
__device__ __align__(16) float G_buf[Bb * Tt * Tt];
__device__ __align__(16) float D_buf[Bb * Tt * Oo];
__device__ __align__(16) float U_buf[Bb * Tt * Oo];
__device__ __align__(16) float H_buf[Bb * CH * Oo];   // per-chunk history
__device__ __align__(16) float P_buf[Bb * Oo];        // running product across chunks
__device__ __align__(16) __nv_bfloat16 Xhi_g[Bb * Tt * Ii];
__device__ __align__(16) __nv_bfloat16 Xlo_g[Bb * Tt * Ii];
__device__ __align__(16) __nv_bfloat16 Whi_g[Bb * Oo * Ii];
__device__ __align__(16) __nv_bfloat16 Wlo_g[Bb * Oo * Ii];

// ---- packed f32x2 helpers ----
__device__ __forceinline__ u64 pack2(float x, float y) {
    u64 r; asm("mov.b64 %0, {%1, %2};" : "=l"(r) : "f"(x), "f"(y)); return r;
}
__device__ __forceinline__ void unpack2(u64 v, float& x, float& y) {
    asm("mov.b64 {%0, %1}, %2;" : "=f"(x), "=f"(y) : "l"(v));
}
__device__ __forceinline__ u64 ffma2(u64 a, u64 b, u64 c) {
    u64 d; asm("fma.rn.f32x2 %0, %1, %2, %3;" : "=l"(d) : "l"(a), "l"(b), "l"(c)); return d;
}

// ---- mma.sync / cp.async helpers ----
__device__ __forceinline__ uint32_t smem_u32(const void* p) {
    uint32_t a;
    asm("{ .reg .u64 t; cvta.to.shared.u64 t, %1; cvt.u32.u64 %0, t; }" : "=r"(a) : "l"(p));
    return a;
}
__device__ __forceinline__ void ldsm4(uint32_t addr, uint32_t r[4]) {
    asm volatile("ldmatrix.sync.aligned.m8n8.x4.shared.b16 {%0,%1,%2,%3}, [%4];"
                 : "=r"(r[0]), "=r"(r[1]), "=r"(r[2]), "=r"(r[3]) : "r"(addr));
}
__device__ __forceinline__ void mma16816(float c[4], const uint32_t a[4],
                                         uint32_t b0, uint32_t b1) {
    asm volatile("mma.sync.aligned.m16n8k16.row.col.f32.bf16.bf16.f32 "
                 "{%0,%1,%2,%3}, {%4,%5,%6,%7}, {%8,%9}, {%0,%1,%2,%3};"
                 : "+f"(c[0]), "+f"(c[1]), "+f"(c[2]), "+f"(c[3])
                 : "r"(a[0]), "r"(a[1]), "r"(a[2]), "r"(a[3]), "r"(b0), "r"(b1));
}
#define CP_ASYNC16(dst, src) asm volatile("cp.async.cg.shared.global [%0], [%1], 16;" :: "r"(dst), "l"(src))
#define CP_COMMIT()          asm volatile("cp.async.commit_group;" ::: "memory")
#define CP_WAIT(n)           asm volatile("cp.async.wait_group %0;" :: "n"(n) : "memory")

#define SWZ(x) ((x) ^ (((x) >> 3) & 0x70))

// ============================================================
// bf16 hi/lo split conversion
// ============================================================
__device__ __forceinline__ void split_store(const float* __restrict__ src,
                                            __nv_bfloat16* __restrict__ hi,
                                            __nv_bfloat16* __restrict__ lo, int i)
{
    float4 v = reinterpret_cast<const float4*>(src)[i];
    __nv_bfloat16 h0 = __float2bfloat16(v.x), h1 = __float2bfloat16(v.y);
    __nv_bfloat16 h2 = __float2bfloat16(v.z), h3 = __float2bfloat16(v.w);
    __nv_bfloat16 l0 = __float2bfloat16(v.x - __bfloat162float(h0));
    __nv_bfloat16 l1 = __float2bfloat16(v.y - __bfloat162float(h1));
    __nv_bfloat16 l2 = __float2bfloat16(v.z - __bfloat162float(h2));
    __nv_bfloat16 l3 = __float2bfloat16(v.w - __bfloat162float(h3));
    reinterpret_cast<__nv_bfloat162*>(hi)[2 * i]     = __nv_bfloat162(h0, h1);
    reinterpret_cast<__nv_bfloat162*>(hi)[2 * i + 1] = __nv_bfloat162(h2, h3);
    reinterpret_cast<__nv_bfloat162*>(lo)[2 * i]     = __nv_bfloat162(l0, l1);
    reinterpret_cast<__nv_bfloat162*>(lo)[2 * i + 1] = __nv_bfloat162(l2, l3);
}

__global__ void __launch_bounds__(256)
split_x(const float* __restrict__ X)
{
    int i = blockIdx.x * 256 + threadIdx.x;
    if (i < Bb * Tt * Ii / 4) split_store(X, Xhi_g, Xlo_g, i);
}

__global__ void __launch_bounds__(256)
split_w(const float* __restrict__ W)
{
    int i = blockIdx.x * 256 + threadIdx.x;
    if (i < Bb * Oo * Ii / 4) split_store(W, Whi_g, Wlo_g, i);
}

// ============================================================
// mma.sync bf16 3-term-split GEMM (byte-identical to R10 run)
// ============================================================
#define KC       64
#define NKC      (Ii / KC)
#define SM_TILE  16384
#define SM_STAGE (4 * SM_TILE)
#define SM_TOTAL (2 * SM_STAGE)

template<int M, int N, bool TRI>
__device__ __forceinline__ void gemm_core(const __nv_bfloat16* __restrict__ AH,
                                          const __nv_bfloat16* __restrict__ AL,
                                          const __nv_bfloat16* __restrict__ BH,
                                          const __nv_bfloat16* __restrict__ BL,
                                          float* __restrict__ Cg)
{
    const int nx = blockIdx.x, my = blockIdx.y, b = blockIdx.z;
    if (TRI && my > nx) return;

    extern __shared__ __align__(1024) char smem[];
    const uint32_t sb = smem_u32(smem);
    const int tid = threadIdx.x;
    const int wid = tid >> 5;
    const int l   = tid & 31;

    const int warp_m = wid & 1;
    const int warp_n = wid >> 1;

    const __nv_bfloat16* gbase[4];
    gbase[0] = AH + ((size_t)b * M + my * 128) * Ii;
    gbase[1] = AL + ((size_t)b * M + my * 128) * Ii;
    gbase[2] = BH + ((size_t)b * N + nx * 128) * Ii;
    gbase[3] = BL + ((size_t)b * N + nx * 128) * Ii;

    int  s_arr[16], s_rw[16], s_un[16];
    uint32_t s_dst[16];
    #pragma unroll
    for (int i = 0; i < 16; i++) {
        const int u = tid + 256 * i;
        s_arr[i] = u >> 10;
        const int rem = u & 1023;
        s_rw[i] = rem >> 3;
        s_un[i] = rem & 7;
        s_dst[i] = (uint32_t)(s_arr[i] * SM_TILE + SWZ(s_rw[i] * 128 + s_un[i] * 16));
    }

    const int g = l >> 3, r = l & 7;
    const uint32_t aoff = (uint32_t)(warp_m * 64 + (g & 1) * 8 + r) * 128;
    const uint32_t akb  = (uint32_t)((g >> 1) * 16);
    const uint32_t boff = (uint32_t)(warp_n * 32 + (g >> 1) * 8 + r) * 128;
    const uint32_t bkb  = (uint32_t)((g & 1) * 16);
    const uint32_t lxor = (uint32_t)(r << 4);

    float c[4][4][4];
    #pragma unroll
    for (int mt = 0; mt < 4; mt++)
        #pragma unroll
        for (int nt = 0; nt < 4; nt++)
            #pragma unroll
            for (int q = 0; q < 4; q++) c[mt][nt][q] = 0.0f;

    #pragma unroll
    for (int i = 0; i < 16; i++) {
        const __nv_bfloat16* src = gbase[s_arr[i]] + (size_t)s_rw[i] * Ii + s_un[i] * 8;
        CP_ASYNC16(sb + s_dst[i], src);
    }
    CP_COMMIT();

    for (int ck = 0; ck < NKC; ck++) {
        const uint32_t buf = sb + (uint32_t)((ck & 1) * SM_STAGE);

        if (ck + 1 < NKC) {
            const uint32_t nbuf = (uint32_t)(((ck + 1) & 1) * SM_STAGE);
            const int koff = (ck + 1) * KC;
            #pragma unroll
            for (int i = 0; i < 16; i++) {
                const __nv_bfloat16* src =
                    gbase[s_arr[i]] + (size_t)s_rw[i] * Ii + koff + s_un[i] * 8;
                CP_ASYNC16(sb + nbuf + s_dst[i], src);
            }
            CP_COMMIT();
            CP_WAIT(1);
        } else {
            CP_WAIT(0);
        }
        __syncthreads();

        const uint32_t As_hi = buf;
        const uint32_t As_lo = buf + SM_TILE;
        const uint32_t Bs_hi = buf + 2 * SM_TILE;
        const uint32_t Bs_lo = buf + 3 * SM_TILE;

        #pragma unroll
        for (int ks = 0; ks < 4; ks++) {
            const uint32_t kb = (uint32_t)(ks * 32);

            uint32_t bh[4][2], bl[4][2];
            #pragma unroll
            for (int nt2 = 0; nt2 < 2; nt2++) {
                uint32_t t4[4];
                const uint32_t badd = boff + nt2 * 2048 + ((kb + bkb) ^ lxor);
                ldsm4(Bs_hi + badd, t4);
                bh[2 * nt2][0] = t4[0]; bh[2 * nt2][1] = t4[1];
                bh[2 * nt2 + 1][0] = t4[2]; bh[2 * nt2 + 1][1] = t4[3];
                ldsm4(Bs_lo + badd, t4);
                bl[2 * nt2][0] = t4[0]; bl[2 * nt2][1] = t4[1];
                bl[2 * nt2 + 1][0] = t4[2]; bl[2 * nt2 + 1][1] = t4[3];
            }

            #pragma unroll
            for (int mt = 0; mt < 4; mt++) {
                const uint32_t aadd = aoff + mt * 2048 + ((kb + akb) ^ lxor);
                uint32_t a4[4];
                ldsm4(As_hi + aadd, a4);
                #pragma unroll
                for (int nt = 0; nt < 4; nt++) {
                    mma16816(c[mt][nt], a4, bh[nt][0], bh[nt][1]);
                    mma16816(c[mt][nt], a4, bl[nt][0], bl[nt][1]);
                }
                ldsm4(As_lo + aadd, a4);
                #pragma unroll
                for (int nt = 0; nt < 4; nt++)
                    mma16816(c[mt][nt], a4, bh[nt][0], bh[nt][1]);
            }
        }
        __syncthreads();
    }

    float* Crow = Cg + ((size_t)b * M + my * 128) * N + nx * 128;
    const int qr = l >> 2, qc = l & 3;
    #pragma unroll
    for (int mt = 0; mt < 4; mt++) {
        const int m0 = warp_m * 64 + mt * 16;
        #pragma unroll
        for (int nt = 0; nt < 4; nt++) {
            const int n0 = warp_n * 32 + nt * 8 + 2 * qc;
            *reinterpret_cast<float2*>(&Crow[(size_t)(m0 + qr) * N + n0]) =
                make_float2(c[mt][nt][0], c[mt][nt][1]);
            *reinterpret_cast<float2*>(&Crow[(size_t)(m0 + qr + 8) * N + n0]) =
                make_float2(c[mt][nt][2], c[mt][nt][3]);
        }
    }
}

__global__ void __launch_bounds__(256, 1)
gemm_g_k() { gemm_core<Tt, Tt, true>(Xhi_g, Xlo_g, Xhi_g, Xlo_g, G_buf); }

__global__ void __launch_bounds__(256, 1)
gemm_d_k() { gemm_core<Tt, Oo, false>(Xhi_g, Xlo_g, Whi_g, Wlo_g, D_buf); }

// ============================================================
// hist_k(c): H[b][tl][o] = sum_{j<t0} G[b][j][t0+tl] * U[b][j][o]
// grid (4 o-tiles, 64 b), 256 threads; thread = (o, half) -> 16 tl outputs.
// ============================================================
__global__ void __launch_bounds__(256)
hist_k(int c)
{
    __shared__ __align__(16) float Gh[(Tt - CH) * CH];   // <= 224*32*4 = 28.7 KB

    const int t0  = c * CH;
    const int tid = threadIdx.x;
    const int b   = blockIdx.y;
    const int o   = blockIdx.x * 128 + (tid & 127);
    const int tg  = (tid >> 7) * 16;                     // 0 or 16

    // stage Gh[j][tl] = G[b][j][t0+tl]  (float4, coalesced)
    const float4* Gb4 = reinterpret_cast<const float4*>(G_buf + (size_t)b * Tt * Tt);
    {
        float4* dst = reinterpret_cast<float4*>(Gh);
        for (int i = tid; i < t0 * 8; i += 256) {
            const int j = i >> 3, q = i & 7;
            dst[i] = Gb4[j * (Tt / 4) + t0 / 4 + q];
        }
    }
    __syncthreads();

    const float* Ub = U_buf + (size_t)b * Tt * Oo + o;

    u64 acc[8];
    #pragma unroll
    for (int q = 0; q < 8; q++) acc[q] = 0;

    for (int j = 0; j < t0; j += 4) {
        float up[4];
        #pragma unroll
        for (int q = 0; q < 4; q++) up[q] = Ub[(j + q) * Oo];
        #pragma unroll
        for (int q = 0; q < 4; q++) {
            const u64 u2 = pack2(up[q], up[q]);
            const u64* grow = reinterpret_cast<const u64*>(&Gh[(j + q) * CH + tg]);
            #pragma unroll
            for (int p = 0; p < 8; p++)
                acc[p] = ffma2(u2, grow[p], acc[p]);
        }
    }

    float* Hb = H_buf + (size_t)b * CH * Oo + o;
    #pragma unroll
    for (int p = 0; p < 8; p++) {
        float lo, hi;
        unpack2(acc[p], lo, hi);
        Hb[(tg + 2 * p)     * Oo] = lo;
        Hb[(tg + 2 * p + 1) * Oo] = hi;
    }
}

// ============================================================
// diag_k(c): the truly serial 32 steps for chunk c.
// grid (4 rg, 64 b), 128 threads (one per row).
// ============================================================
__global__ void __launch_bounds__(128)
diag_k(int c, const int* __restrict__ obs, float* __restrict__ out)
{
    __shared__ __align__(16) float Gd[CH * CH];   // [jl][tl], 4 KB
    __shared__ float y_s[CH * 129];               // 16.5 KB

    const int t0  = c * CH;
    const int tid = threadIdx.x;
    const int rg  = blockIdx.x;
    const int b   = blockIdx.y;
    const int o   = rg * 128 + tid;

    const int  slot_o = obs[tid];
    const bool have   = ((slot_o >> 7) == rg);
    const int  lrow   = slot_o & 127;

    // stage Gd[jl][tl] = G[b][t0+jl][t0+tl]
    const float4* Gb4 = reinterpret_cast<const float4*>(G_buf + (size_t)b * Tt * Tt);
    {
        float4* dst = reinterpret_cast<float4*>(Gd);
        for (int i = tid; i < CH * 8; i += 128) {
            const int j = i >> 3, q = i & 7;
            dst[i] = Gb4[(t0 + j) * (Tt / 4) + t0 / 4 + q];
        }
    }

    // prefetch H, D, P (independent LDGs; overlap staging)
    const float* Db = D_buf + (size_t)b * Tt * Oo + o;
    const float* Hb = H_buf + (size_t)b * CH * Oo + o;
    float dv[CH], h[CH];
    #pragma unroll
    for (int tl = 0; tl < CH; tl++) dv[tl] = Db[(t0 + tl) * Oo];
    if (c > 0) {
        #pragma unroll
        for (int tl = 0; tl < CH; tl++) h[tl] = Hb[tl * Oo];
    } else {
        #pragma unroll
        for (int tl = 0; tl < CH; tl++) h[tl] = 0.0f;
    }
    float P = (c > 0) ? P_buf[b * Oo + o] : 1.0f;

    __syncthreads();

    float* Ub = U_buf + (size_t)b * Tt * Oo + o;
    float uc[CH];
    #pragma unroll
    for (int tl = 0; tl < CH; tl++) {
        float S = h[tl];
        #pragma unroll
        for (int jl = 0; jl < tl; jl++)
            S = fmaf(uc[jl], Gd[jl * CH + tl], S);
        const float pre = P * (dv[tl] + S);
        const float y   = 1.0f / (1.0f + __expf(-pre));
        const float c1  = 1.0f - ETA * y * y;
        P *= c1;
        const float u = __fdividef(ETA * y, P);
        uc[tl] = u;
        Ub[(t0 + tl) * Oo] = u;
        y_s[tl * 129 + tid] = y;
    }
    P_buf[b * Oo + o] = P;
    __syncthreads();

    if (have) {
        float* outb = out + (size_t)b * Tt * NOBS;
        #pragma unroll 4
        for (int tl = 0; tl < CH; tl++)
            outb[(t0 + tl) * NOBS + tid] = y_s[tl * 129 + lrow];
    }
}

extern "C" void kernel_launch(void* const* d_in, const int* in_sizes, int n_in,
                              void* d_out, int out_size)
{
    const float* X  = (const float*)d_in[0];
    const float* Wi = (const float*)d_in[1];
    const int* obs  = (const int*)d_in[2];
    float* out      = (float*)d_out;

    cudaFuncSetAttribute(gemm_g_k, cudaFuncAttributeMaxDynamicSharedMemorySize, SM_TOTAL);
    cudaFuncSetAttribute(gemm_d_k, cudaFuncAttributeMaxDynamicSharedMemorySize, SM_TOTAL);

    const int nX4 = Bb * Tt * Ii / 4;
    const int nW4 = Bb * Oo * Ii / 4;
    split_x<<<(nX4 + 255) / 256, 256>>>(X);
    split_w<<<(nW4 + 255) / 256, 256>>>(Wi);

    gemm_g_k<<<dim3(Tt / 128, Tt / 128, Bb), 256, SM_TOTAL>>>();
    gemm_d_k<<<dim3(Oo / 128, Tt / 128, Bb), 256, SM_TOTAL>>>();

    for (int c = 0; c < NCH; c++) {
        if (c > 0) hist_k<<<dim3(4, Bb), 256>>>(c);
        diag_k<<<dim3(4, Bb), 128>>>(c, obs, out);
    }
}